// round 9
// baseline (speedup 1.0000x reference)
#include <cuda_runtime.h>

#define Bn 32
#define Tn 2048
#define Fn 2048
#define DQn 1024
#define UNITSn 1024
#define HALFn 1024      // F/2
#define CONCATn 2048    // HALF + DQ
#define NROWS (Bn * Tn) // 65536
#define GMAIN 296       // 2 blocks per SM exactly (148 SMs)
#define PAIRS 4         // warp pairs per block (8 warps, 256 threads)

// Scratch (allocation-free rule: __device__ globals)
__device__ float g_w[CONCATn];                 // W1 @ V
__device__ float g_bias;                       // b1·V + bV
__device__ float g_qbv[Bn];                    // per-batch qb
__device__ float g_score[NROWS];               // raw scores (indexed by global row)
__device__ float g_partial[2 * GMAIN * Fn];    // per-(block,subrange) ctx partials
__device__ float g_pm[2 * GMAIN];              // per-slot max
__device__ float g_pZ[2 * GMAIN];              // per-slot exp-sum at max
__device__ int   g_cnt[Bn];                    // per-batch arrival counter (self-reset)
__device__ int   g_wcnt;                       // k_w completion counter (self-reset)

// row -> owning block (inverse of r0(g) = g*65536/296)
__device__ __forceinline__ int blk_of_row(int r) {
    return (int)(((long long)(r + 1) * GMAIN - 1) >> 16);
}
__device__ __forceinline__ int row0_of_blk(int g) {
    return (int)(((long long)g << 16) / GMAIN);
}

// ---------------------------------------------------------------------------
// K1: w = W1@V (warp per c); extra block: bias = b1·V + bV.
//     Last-arriving block computes per-batch qbv = query[b]·w[1024:] + bias.
// ---------------------------------------------------------------------------
__global__ void k_w(const float* __restrict__ W1, const float* __restrict__ V,
                    const float* __restrict__ b1, const float* __restrict__ bV,
                    const float* __restrict__ query) {
    __shared__ int s_go;
    int tid = threadIdx.x, warp = tid >> 5, lane = tid & 31;

    if (blockIdx.x == CONCATn / 8) {
        if (warp == 0) {
            const float4* b4 = reinterpret_cast<const float4*>(b1);
            const float4* v4 = reinterpret_cast<const float4*>(V);
            float acc = 0.f;
#pragma unroll
            for (int i = 0; i < UNITSn / 128; i++) {
                float4 a = b4[lane + i * 32];
                float4 b = v4[lane + i * 32];
                acc += a.x * b.x + a.y * b.y + a.z * b.z + a.w * b.w;
            }
#pragma unroll
            for (int o = 16; o; o >>= 1) acc += __shfl_xor_sync(0xffffffffu, acc, o);
            if (lane == 0) g_bias = acc + bV[0];
        }
    } else {
        int wc = blockIdx.x * 8 + warp;
        const float4* row = reinterpret_cast<const float4*>(W1 + (size_t)wc * UNITSn);
        const float4* v4  = reinterpret_cast<const float4*>(V);
        float acc = 0.f;
#pragma unroll
        for (int i = 0; i < UNITSn / 128; i++) {
            float4 a = row[lane + i * 32];
            float4 b = v4[lane + i * 32];
            acc += a.x * b.x + a.y * b.y + a.z * b.z + a.w * b.w;
        }
#pragma unroll
        for (int o = 16; o; o >>= 1) acc += __shfl_xor_sync(0xffffffffu, acc, o);
        if (lane == 0) g_w[wc] = acc;
    }

    // ---- last-arriving block computes qbv for all batches ----
    __threadfence();
    __syncthreads();
    if (tid == 0) s_go = (atomicAdd(&g_wcnt, 1) == (CONCATn / 8 + 1) - 1);
    __syncthreads();
    if (!s_go) return;
    __threadfence();

    const float4* wu = reinterpret_cast<const float4*>(g_w + HALFn);
    for (int b = warp; b < Bn; b += 8) {
        const float4* q4 = reinterpret_cast<const float4*>(query + (size_t)b * DQn);
        float acc = 0.f;
#pragma unroll
        for (int i = 0; i < DQn / 128; i++) {
            float4 q = q4[lane + i * 32];
            float4 w = wu[lane + i * 32];
            acc += q.x * w.x + q.y * w.y + q.z * w.z + q.w * w.w;
        }
#pragma unroll
        for (int o = 16; o; o >>= 1) acc += __shfl_xor_sync(0xffffffffu, acc, o);
        if (lane == 0) g_qbv[b] = acc + g_bias;
    }
    if (tid == 0) g_wcnt = 0;   // reset for next replay
}

// ---------------------------------------------------------------------------
// K2 (k_main): 296 blocks, each streams an even share of the 65536 rows
//   (221-222 rows, up to 2 batch sub-ranges). Warp-pair specialized.
//   Per-batch threadfence-counter epilogue with analytic arrival counts.
// ---------------------------------------------------------------------------
__global__ __launch_bounds__(256, 2) void k_main(const float* __restrict__ values,
                                                 float* __restrict__ ctx,
                                                 float* __restrict__ aw) {
    __shared__ float sw[HALFn];                   // 4 KB: w[:1024]
    __shared__ float s_e[2][PAIRS], s_c[2][PAIRS];
    __shared__ float s_m[PAIRS], s_Z[PAIRS];
    __shared__ float swacc[PAIRS * HALFn];        // 16 KB merge buffer
    __shared__ int   s_last;

    int g = blockIdx.x;
    int tid = threadIdx.x, warp = tid >> 5, lane = tid & 31;
    int pair = warp >> 1;
    bool isA = (warp & 1) == 0;
    int barid = 1 + pair;

    for (int i = tid; i < HALFn; i += 256) sw[i] = g_w[i];
    __syncthreads();
    const float4* w4 = reinterpret_cast<const float4*>(sw);

    int r0 = row0_of_blk(g);
    int r1 = row0_of_blk(g + 1);

#pragma unroll 1
    for (int k = 0; k < 2; k++) {
        if (r0 >= r1) break;
        int b = r0 >> 11;
        int bend = (b + 1) << 11;
        if (bend > r1) bend = r1;
        int L = bend - r0;                 // rows in this sub-range
        float qb = g_qbv[b];
        const float* base = values + (size_t)r0 * Fn;

        float4 acc[8];
#pragma unroll
        for (int i = 0; i < 8; i++) acc[i] = make_float4(0.f, 0.f, 0.f, 0.f);
        float m = -1e30f, Z = 0.f;

        if (isA) {
            int it = 0;
#pragma unroll 1
            for (int local = pair; local < L; local += PAIRS, it++) {
                const float4* rp = reinterpret_cast<const float4*>(
                    base + (size_t)local * Fn);
                float4 v[8];
#pragma unroll
                for (int i = 0; i < 8; i++) v[i] = rp[lane + 32 * i];
                float d = 0.f;
#pragma unroll
                for (int i = 0; i < 8; i++) {
                    float4 w = w4[lane + 32 * i];
                    d += v[i].x * w.x + v[i].y * w.y + v[i].z * w.z + v[i].w * w.w;
                }
#pragma unroll
                for (int o = 16; o; o >>= 1) d += __shfl_xor_sync(0xffffffffu, d, o);
                float s = d + qb;
                if (lane == 0) g_score[r0 + local] = s;

                float c = 1.f;
                if (s > m) {               // warp-uniform
                    c = __expf(m - s);
                    m = s;
                    Z *= c;
                }
                float e = __expf(s - m);
                Z += e;
                if (lane == 0) { s_e[it & 1][pair] = e; s_c[it & 1][pair] = c; }
                asm volatile("bar.sync %0, 64;" :: "r"(barid) : "memory");

                if (c != 1.f) {
#pragma unroll
                    for (int i = 0; i < 8; i++) {
                        acc[i].x *= c; acc[i].y *= c; acc[i].z *= c; acc[i].w *= c;
                    }
                }
#pragma unroll
                for (int i = 0; i < 8; i++) {
                    acc[i].x += e * v[i].x; acc[i].y += e * v[i].y;
                    acc[i].z += e * v[i].z; acc[i].w += e * v[i].w;
                }
            }
            if (lane == 0) { s_m[pair] = m; s_Z[pair] = Z; }
        } else {
            int it = 0;
#pragma unroll 1
            for (int local = pair; local < L; local += PAIRS, it++) {
                const float4* rp = reinterpret_cast<const float4*>(
                    base + (size_t)local * Fn + HALFn);
                float4 v[8];
#pragma unroll
                for (int i = 0; i < 8; i++) v[i] = rp[lane + 32 * i];  // overlap A
                asm volatile("bar.sync %0, 64;" :: "r"(barid) : "memory");
                float e = s_e[it & 1][pair];
                float c = s_c[it & 1][pair];
                if (c != 1.f) {
#pragma unroll
                    for (int i = 0; i < 8; i++) {
                        acc[i].x *= c; acc[i].y *= c; acc[i].z *= c; acc[i].w *= c;
                    }
                }
#pragma unroll
                for (int i = 0; i < 8; i++) {
                    acc[i].x += e * v[i].x; acc[i].y += e * v[i].y;
                    acc[i].z += e * v[i].z; acc[i].w += e * v[i].w;
                }
            }
        }
        __syncthreads();

        // ---- merge 4 pairs into this sub-range's partial slot ----
        float mseg = s_m[0];
#pragma unroll
        for (int p = 1; p < PAIRS; p++) mseg = fmaxf(mseg, s_m[p]);
        float wt[PAIRS];
        float Zseg = 0.f;
#pragma unroll
        for (int p = 0; p < PAIRS; p++) {
            wt[p] = __expf(s_m[p] - mseg);
            Zseg += s_Z[p] * wt[p];
        }

        int slot = 2 * g + k;
        float* part = g_partial + (size_t)slot * Fn;

        if (isA) {
#pragma unroll
            for (int i = 0; i < 8; i++)
                *reinterpret_cast<float4*>(&swacc[pair * HALFn + 4 * (lane + 32 * i)]) = acc[i];
        }
        __syncthreads();
        {
            float4 r = make_float4(0.f, 0.f, 0.f, 0.f);
#pragma unroll
            for (int p = 0; p < PAIRS; p++) {
                float4 c = *reinterpret_cast<const float4*>(&swacc[p * HALFn + 4 * tid]);
                r.x += wt[p] * c.x; r.y += wt[p] * c.y;
                r.z += wt[p] * c.z; r.w += wt[p] * c.w;
            }
            *reinterpret_cast<float4*>(&part[4 * tid]) = r;
        }
        __syncthreads();
        if (!isA) {
#pragma unroll
            for (int i = 0; i < 8; i++)
                *reinterpret_cast<float4*>(&swacc[pair * HALFn + 4 * (lane + 32 * i)]) = acc[i];
        }
        __syncthreads();
        {
            float4 r = make_float4(0.f, 0.f, 0.f, 0.f);
#pragma unroll
            for (int p = 0; p < PAIRS; p++) {
                float4 c = *reinterpret_cast<const float4*>(&swacc[p * HALFn + 4 * tid]);
                r.x += wt[p] * c.x; r.y += wt[p] * c.y;
                r.z += wt[p] * c.z; r.w += wt[p] * c.w;
            }
            *reinterpret_cast<float4*>(&part[HALFn + 4 * tid]) = r;
        }
        if (tid == 0) { g_pm[slot] = mseg; g_pZ[slot] = Zseg; }

        // ---- per-batch arrival; last combiner runs the epilogue ----
        __threadfence();
        __syncthreads();
        int firstblk = blk_of_row(b << 11);
        int lastblk  = blk_of_row((b << 11) + Tn - 1);
        int nseg = lastblk - firstblk + 1;
        if (tid == 0) {
            int prev = atomicAdd(&g_cnt[b], 1);
            s_last = (prev == nseg - 1);
        }
        __syncthreads();
        if (s_last) {
            __threadfence();   // acquire: peer partials + scores

            float gm = -1e30f;
            for (int gg = firstblk; gg <= lastblk; gg++) {
                int kk = ((row0_of_blk(gg) >> 11) == b) ? 0 : 1;
                gm = fmaxf(gm, g_pm[2 * gg + kk]);
            }
            float Zg = 0.f;
            for (int gg = firstblk; gg <= lastblk; gg++) {
                int kk = ((row0_of_blk(gg) >> 11) == b) ? 0 : 1;
                Zg += g_pZ[2 * gg + kk] * __expf(g_pm[2 * gg + kk] - gm);
            }
            float inv = 1.0f / Zg;

            float4 c0 = make_float4(0.f, 0.f, 0.f, 0.f);
            float4 c1 = make_float4(0.f, 0.f, 0.f, 0.f);
            for (int gg = firstblk; gg <= lastblk; gg++) {
                int kk = ((row0_of_blk(gg) >> 11) == b) ? 0 : 1;
                float w = __expf(g_pm[2 * gg + kk] - gm) * inv;
                const float* ps = g_partial + (size_t)(2 * gg + kk) * Fn;
                float4 p0 = *reinterpret_cast<const float4*>(&ps[4 * tid]);
                float4 p1 = *reinterpret_cast<const float4*>(&ps[HALFn + 4 * tid]);
                c0.x += w * p0.x; c0.y += w * p0.y; c0.z += w * p0.z; c0.w += w * p0.w;
                c1.x += w * p1.x; c1.y += w * p1.y; c1.z += w * p1.z; c1.w += w * p1.w;
            }
            *reinterpret_cast<float4*>(&ctx[(size_t)b * Fn + 4 * tid]) = c0;
            *reinterpret_cast<float4*>(&ctx[(size_t)b * Fn + HALFn + 4 * tid]) = c1;

#pragma unroll
            for (int h = 0; h < 2; h++) {
                int off = h * 1024 + 4 * tid;
                float4 sc = *reinterpret_cast<const float4*>(&g_score[(b << 11) + off]);
                float4 r;
                r.x = __expf(sc.x - gm) * inv;
                r.y = __expf(sc.y - gm) * inv;
                r.z = __expf(sc.z - gm) * inv;
                r.w = __expf(sc.w - gm) * inv;
                *reinterpret_cast<float4*>(&aw[(size_t)b * Tn + off]) = r;
            }
            if (tid == 0) g_cnt[b] = 0;   // reset for next replay
        }
        __syncthreads();   // protect swacc before next sub-range
        r0 = bend;
    }
}

// ---------------------------------------------------------------------------
extern "C" void kernel_launch(void* const* d_in, const int* in_sizes, int n_in,
                              void* d_out, int out_size) {
    const float* query  = (const float*)d_in[0];
    const float* values = (const float*)d_in[1];
    const float* W1     = (const float*)d_in[2];
    const float* b1     = (const float*)d_in[3];
    const float* V      = (const float*)d_in[4];
    const float* bV     = (const float*)d_in[5];

    float* out = (float*)d_out;
    float* ctx = out;                 // [B, F]   context_vector (32,1,2048)
    float* aw  = out + Bn * Fn;       // [B, T]   attention_weights (32,2048,1)

    k_w<<<CONCATn / 8 + 1, 256>>>(W1, V, b1, bV, query);
    k_main<<<GMAIN, 256>>>(values, ctx, aw);
}

// round 10
// speedup vs baseline: 1.1290x; 1.1290x over previous
#include <cuda_runtime.h>

#define Bn 32
#define Tn 2048
#define Fn 2048
#define DQn 1024
#define UNITSn 1024
#define HALFn 1024      // F/2
#define CONCATn 2048    // HALF + DQ
#define SEG 8           // T segments per batch -> grid 256 = single wave
#define TS (Tn / SEG)   // 256 rows per segment block
#define PAIRS 4         // warp pairs per block (8 warps, 256 threads)
#define RPP (TS / PAIRS) // 64 rows per pair
#define NBLK (SEG * Bn) // 256

// Scratch (allocation-free rule: __device__ globals)
__device__ float g_w[CONCATn];               // W1 @ V
__device__ float g_bias;                     // b1·V + bV
__device__ float g_score[Bn * Tn];           // raw scores
__device__ float g_partial[Bn * SEG * Fn];   // per-seg ctx partials (scale e^{m_seg})
__device__ float g_m[Bn * SEG];              // per-segment max
__device__ float g_Z[Bn * SEG];              // per-segment exp-sum at m_seg
__device__ int   g_cnt[Bn];                  // per-batch arrival counter (self-reset)
__device__ int   g_syncw;                    // w-phase arrival counter
__device__ int   g_done;                     // end-of-kernel counter (resets g_syncw)

// ---------------------------------------------------------------------------
// Single fused kernel: phase-0 computes w = W1@V (+bias) cooperatively across
// the 256 resident blocks (single wave -> spin is deadlock-free), then the
// R8 warp-pair-specialized single-pass attention with fused combine epilogue.
// ---------------------------------------------------------------------------
__global__ __launch_bounds__(256, 2) void k_all(const float* __restrict__ values,
                                                const float* __restrict__ query,
                                                const float* __restrict__ W1,
                                                const float* __restrict__ V,
                                                const float* __restrict__ b1,
                                                const float* __restrict__ bV,
                                                float* __restrict__ ctx,
                                                float* __restrict__ aw) {
    __shared__ float sw[HALFn];                   // 4 KB: w[:1024]
    __shared__ float s_e[2][PAIRS], s_c[2][PAIRS];
    __shared__ float s_m[PAIRS], s_Z[PAIRS];
    __shared__ float swacc[PAIRS * HALFn];        // 16 KB merge buffer
    __shared__ float red[8];
    __shared__ int   s_last;

    int seg = blockIdx.x, b = blockIdx.y;
    int bid = b * SEG + seg;                      // 0..255
    int tid = threadIdx.x, warp = tid >> 5, lane = tid & 31;
    int pair = warp >> 1;
    bool isA = (warp & 1) == 0;
    int barid = 1 + pair;

    // ================= phase 0: cooperative w = W1 @ V =================
    {
        int wc = bid * 8 + warp;                  // 0..2047
        const float4* row = reinterpret_cast<const float4*>(W1 + (size_t)wc * UNITSn);
        const float4* v4  = reinterpret_cast<const float4*>(V);
        float acc = 0.f;
#pragma unroll
        for (int i = 0; i < UNITSn / 128; i++) {
            float4 a = row[lane + i * 32];
            float4 v = v4[lane + i * 32];
            acc += a.x * v.x + a.y * v.y + a.z * v.z + a.w * v.w;
        }
#pragma unroll
        for (int o = 16; o; o >>= 1) acc += __shfl_xor_sync(0xffffffffu, acc, o);
        if (lane == 0) g_w[wc] = acc;

        if (bid == 0 && warp == 0) {              // bias = b1·V + bV
            const float4* b4 = reinterpret_cast<const float4*>(b1);
            float ba = 0.f;
#pragma unroll
            for (int i = 0; i < UNITSn / 128; i++) {
                float4 a = b4[lane + i * 32];
                float4 v = v4[lane + i * 32];
                ba += a.x * v.x + a.y * v.y + a.z * v.z + a.w * v.w;
            }
#pragma unroll
            for (int o = 16; o; o >>= 1) ba += __shfl_xor_sync(0xffffffffu, ba, o);
            if (lane == 0) g_bias = ba + bV[0];
        }
    }
    __threadfence();
    __syncthreads();
    if (tid == 0) {
        atomicAdd(&g_syncw, 1);
        while (atomicAdd(&g_syncw, 0) < NBLK) __nanosleep(64);
    }
    __syncthreads();
    __threadfence();   // acquire: all g_w / g_bias writes visible

    // ================= prologue: sw + qb =================
    for (int i = tid; i < HALFn; i += 256) sw[i] = g_w[i];
    {
        float4 q = reinterpret_cast<const float4*>(query + (size_t)b * DQn)[tid];
        float4 w = reinterpret_cast<const float4*>(g_w + HALFn)[tid];
        float p = q.x * w.x + q.y * w.y + q.z * w.z + q.w * w.w;
#pragma unroll
        for (int o = 16; o; o >>= 1) p += __shfl_xor_sync(0xffffffffu, p, o);
        if (lane == 0) red[warp] = p;
    }
    __syncthreads();
    float qb = g_bias;
#pragma unroll
    for (int i = 0; i < 8; i++) qb += red[i];

    int tbase = seg * TS;
    const float* base = values + ((size_t)(b * Tn + tbase)) * Fn;
    const float4* w4 = reinterpret_cast<const float4*>(sw);

    float4 acc[8];
#pragma unroll
    for (int i = 0; i < 8; i++) acc[i] = make_float4(0.f, 0.f, 0.f, 0.f);
    float m = -1e30f, Z = 0.f;

    // ================= streaming loop (R8) =================
    if (isA) {
#pragma unroll 1
        for (int r = 0; r < RPP; r++) {
            int row = r * PAIRS + pair;
            const float4* rp = reinterpret_cast<const float4*>(base + (size_t)row * Fn);
            float4 v[8];
#pragma unroll
            for (int i = 0; i < 8; i++) v[i] = __ldcs(&rp[lane + 32 * i]);
            float d = 0.f;
#pragma unroll
            for (int i = 0; i < 8; i++) {
                float4 w = w4[lane + 32 * i];
                d += v[i].x * w.x + v[i].y * w.y + v[i].z * w.z + v[i].w * w.w;
            }
#pragma unroll
            for (int o = 16; o; o >>= 1) d += __shfl_xor_sync(0xffffffffu, d, o);
            float s = d + qb;
            if (lane == 0) g_score[b * Tn + tbase + row] = s;

            float c = 1.f;
            if (s > m) {                 // warp-uniform
                c = __expf(m - s);
                m = s;
                Z *= c;
            }
            float e = __expf(s - m);
            Z += e;
            if (lane == 0) { s_e[r & 1][pair] = e; s_c[r & 1][pair] = c; }
            asm volatile("bar.sync %0, 64;" :: "r"(barid) : "memory");

            if (c != 1.f) {
#pragma unroll
                for (int i = 0; i < 8; i++) {
                    acc[i].x *= c; acc[i].y *= c; acc[i].z *= c; acc[i].w *= c;
                }
            }
#pragma unroll
            for (int i = 0; i < 8; i++) {
                acc[i].x += e * v[i].x; acc[i].y += e * v[i].y;
                acc[i].z += e * v[i].z; acc[i].w += e * v[i].w;
            }
        }
        if (lane == 0) { s_m[pair] = m; s_Z[pair] = Z; }
    } else {
#pragma unroll 1
        for (int r = 0; r < RPP; r++) {
            int row = r * PAIRS + pair;
            const float4* rp = reinterpret_cast<const float4*>(
                base + (size_t)row * Fn + HALFn);
            float4 v[8];
#pragma unroll
            for (int i = 0; i < 8; i++) v[i] = __ldcs(&rp[lane + 32 * i]);  // overlap A
            asm volatile("bar.sync %0, 64;" :: "r"(barid) : "memory");
            float e = s_e[r & 1][pair];
            float c = s_c[r & 1][pair];
            if (c != 1.f) {
#pragma unroll
                for (int i = 0; i < 8; i++) {
                    acc[i].x *= c; acc[i].y *= c; acc[i].z *= c; acc[i].w *= c;
                }
            }
#pragma unroll
            for (int i = 0; i < 8; i++) {
                acc[i].x += e * v[i].x; acc[i].y += e * v[i].y;
                acc[i].z += e * v[i].z; acc[i].w += e * v[i].w;
            }
        }
    }
    __syncthreads();

    // ---- merge 4 pairs into segment partial ----
    float mseg = s_m[0];
#pragma unroll
    for (int p = 1; p < PAIRS; p++) mseg = fmaxf(mseg, s_m[p]);
    float wt[PAIRS];
    float Zseg = 0.f;
#pragma unroll
    for (int p = 0; p < PAIRS; p++) {
        wt[p] = __expf(s_m[p] - mseg);
        Zseg += s_Z[p] * wt[p];
    }

    float* part = g_partial + ((size_t)(b * SEG + seg)) * Fn;

    if (isA) {
#pragma unroll
        for (int i = 0; i < 8; i++)
            *reinterpret_cast<float4*>(&swacc[pair * HALFn + 4 * (lane + 32 * i)]) = acc[i];
    }
    __syncthreads();
    {
        float4 r = make_float4(0.f, 0.f, 0.f, 0.f);
#pragma unroll
        for (int p = 0; p < PAIRS; p++) {
            float4 c = *reinterpret_cast<const float4*>(&swacc[p * HALFn + 4 * tid]);
            r.x += wt[p] * c.x; r.y += wt[p] * c.y;
            r.z += wt[p] * c.z; r.w += wt[p] * c.w;
        }
        *reinterpret_cast<float4*>(&part[4 * tid]) = r;
    }
    __syncthreads();
    if (!isA) {
#pragma unroll
        for (int i = 0; i < 8; i++)
            *reinterpret_cast<float4*>(&swacc[pair * HALFn + 4 * (lane + 32 * i)]) = acc[i];
    }
    __syncthreads();
    {
        float4 r = make_float4(0.f, 0.f, 0.f, 0.f);
#pragma unroll
        for (int p = 0; p < PAIRS; p++) {
            float4 c = *reinterpret_cast<const float4*>(&swacc[p * HALFn + 4 * tid]);
            r.x += wt[p] * c.x; r.y += wt[p] * c.y;
            r.z += wt[p] * c.z; r.w += wt[p] * c.w;
        }
        *reinterpret_cast<float4*>(&part[HALFn + 4 * tid]) = r;
    }

    if (tid == 0) {
        g_m[b * SEG + seg] = mseg;
        g_Z[b * SEG + seg] = Zseg;
    }

    // ---- fused epilogue: last-arriving block per batch combines ----
    __threadfence();
    __syncthreads();
    if (tid == 0) {
        int prev = atomicAdd(&g_cnt[b], 1);
        s_last = (prev == SEG - 1);
    }
    __syncthreads();
    if (s_last) {
        __threadfence();   // acquire side: partials/scores from peer blocks

        float gm = -1e30f;
#pragma unroll
        for (int s = 0; s < SEG; s++) gm = fmaxf(gm, g_m[b * SEG + s]);
        float Zg = 0.f;
#pragma unroll
        for (int s = 0; s < SEG; s++) Zg += g_Z[b * SEG + s] * __expf(g_m[b * SEG + s] - gm);
        float inv = 1.0f / Zg;

        // context: thread tid owns cols 4*tid and 1024+4*tid
        float4 c0 = make_float4(0.f, 0.f, 0.f, 0.f);
        float4 c1 = make_float4(0.f, 0.f, 0.f, 0.f);
#pragma unroll
        for (int s = 0; s < SEG; s++) {
            float w = __expf(g_m[b * SEG + s] - gm) * inv;
            const float* ps = g_partial + ((size_t)(b * SEG + s)) * Fn;
            float4 p0 = *reinterpret_cast<const float4*>(&ps[4 * tid]);
            float4 p1 = *reinterpret_cast<const float4*>(&ps[HALFn + 4 * tid]);
            c0.x += w * p0.x; c0.y += w * p0.y; c0.z += w * p0.z; c0.w += w * p0.w;
            c1.x += w * p1.x; c1.y += w * p1.y; c1.z += w * p1.z; c1.w += w * p1.w;
        }
        *reinterpret_cast<float4*>(&ctx[(size_t)b * Fn + 4 * tid]) = c0;
        *reinterpret_cast<float4*>(&ctx[(size_t)b * Fn + HALFn + 4 * tid]) = c1;

        // attention weights: thread tid owns t = 4*tid and 1024+4*tid
#pragma unroll
        for (int h = 0; h < 2; h++) {
            int off = h * 1024 + 4 * tid;
            float4 sc = *reinterpret_cast<const float4*>(&g_score[b * Tn + off]);
            float4 r;
            r.x = __expf(sc.x - gm) * inv;
            r.y = __expf(sc.y - gm) * inv;
            r.z = __expf(sc.z - gm) * inv;
            r.w = __expf(sc.w - gm) * inv;
            *reinterpret_cast<float4*>(&aw[b * Tn + off]) = r;
        }

        if (tid == 0) g_cnt[b] = 0;   // reset for next graph replay
    }

    // ---- end-of-kernel reset of the w-phase counter (replay safety) ----
    if (tid == 0) {
        int d = atomicAdd(&g_done, 1);
        if (d == NBLK - 1) {
            g_syncw = 0;
            __threadfence();
            g_done = 0;
        }
    }
}

// ---------------------------------------------------------------------------
extern "C" void kernel_launch(void* const* d_in, const int* in_sizes, int n_in,
                              void* d_out, int out_size) {
    const float* query  = (const float*)d_in[0];
    const float* values = (const float*)d_in[1];
    const float* W1     = (const float*)d_in[2];
    const float* b1     = (const float*)d_in[3];
    const float* V      = (const float*)d_in[4];
    const float* bV     = (const float*)d_in[5];

    float* out = (float*)d_out;
    float* ctx = out;                 // [B, F]   context_vector (32,1,2048)
    float* aw  = out + Bn * Fn;       // [B, T]   attention_weights (32,2048,1)

    dim3 g(SEG, Bn);
    k_all<<<g, 256>>>(values, query, W1, V, b1, bV, ctx, aw);
}

// round 12
// speedup vs baseline: 1.1526x; 1.0209x over previous
#include <cuda_runtime.h>

#define Bn 32
#define Tn 2048
#define Fn 2048
#define DQn 1024
#define UNITSn 1024
#define HALFn 1024      // F/2
#define CONCATn 2048    // HALF + DQ
#define SEG 8           // T segments per batch -> grid 256 = single wave
#define TS (Tn / SEG)   // 256 rows per segment block
#define PAIRS 4         // warp pairs per block (8 warps, 256 threads)
#define RPP (TS / PAIRS) // 64 rows per pair
#define NBLK (SEG * Bn) // 256

// Scratch (allocation-free rule: __device__ globals)
__device__ float g_w[CONCATn];               // W1 @ V
__device__ float g_bias;                     // b1·V + bV
__device__ float g_score[Bn * Tn];           // raw scores
__device__ float g_partial[Bn * SEG * Fn];   // per-seg ctx partials (scale e^{m_seg})
__device__ float g_m[Bn * SEG];              // per-segment max
__device__ float g_Z[Bn * SEG];              // per-segment exp-sum at m_seg
__device__ int   g_cnt[Bn];                  // per-batch arrival counter (self-reset)
__device__ int   g_syncw;                    // w-phase arrival counter
__device__ int   g_done;                     // end-of-kernel counter (resets g_syncw)

#define LD8(dst, ptr)                                            \
    do {                                                         \
        _Pragma("unroll")                                        \
        for (int _i = 0; _i < 8; _i++)                           \
            dst[_i] = __ldcs(&(ptr)[lane + 32 * _i]);            \
    } while (0)

// ---------------------------------------------------------------------------
// Single fused kernel: phase-0 cooperative w = W1@V (+bias), then warp-pair
// specialized single-pass attention with DOUBLE-BUFFERED register prefetch
// (next row's loads in flight across the whole dot/barrier/acc chain),
// fused combine epilogue.
// ---------------------------------------------------------------------------
__global__ __launch_bounds__(256, 2) void k_all(const float* __restrict__ values,
                                                const float* __restrict__ query,
                                                const float* __restrict__ W1,
                                                const float* __restrict__ V,
                                                const float* __restrict__ b1,
                                                const float* __restrict__ bV,
                                                float* __restrict__ ctx,
                                                float* __restrict__ aw) {
    __shared__ float sw[HALFn];                   // 4 KB: w[:1024]
    __shared__ float s_e[2][PAIRS], s_c[2][PAIRS];
    __shared__ float s_m[PAIRS], s_Z[PAIRS];
    __shared__ float swacc[PAIRS * HALFn];        // 16 KB merge buffer
    __shared__ float red[8];
    __shared__ int   s_last;

    int seg = blockIdx.x, b = blockIdx.y;
    int bid = b * SEG + seg;                      // 0..255
    int tid = threadIdx.x, warp = tid >> 5, lane = tid & 31;
    int pair = warp >> 1;
    bool isA = (warp & 1) == 0;
    int barid = 1 + pair;

    // ================= phase 0: cooperative w = W1 @ V =================
    {
        int wc = bid * 8 + warp;                  // 0..2047
        const float4* row = reinterpret_cast<const float4*>(W1 + (size_t)wc * UNITSn);
        const float4* v4  = reinterpret_cast<const float4*>(V);
        float acc = 0.f;
#pragma unroll
        for (int i = 0; i < UNITSn / 128; i++) {
            float4 a = row[lane + i * 32];
            float4 v = v4[lane + i * 32];
            acc += a.x * v.x + a.y * v.y + a.z * v.z + a.w * v.w;
        }
#pragma unroll
        for (int o = 16; o; o >>= 1) acc += __shfl_xor_sync(0xffffffffu, acc, o);
        if (lane == 0) g_w[wc] = acc;

        if (bid == 0 && warp == 0) {              // bias = b1·V + bV
            const float4* b4 = reinterpret_cast<const float4*>(b1);
            float ba = 0.f;
#pragma unroll
            for (int i = 0; i < UNITSn / 128; i++) {
                float4 a = b4[lane + i * 32];
                float4 v = v4[lane + i * 32];
                ba += a.x * v.x + a.y * v.y + a.z * v.z + a.w * v.w;
            }
#pragma unroll
            for (int o = 16; o; o >>= 1) ba += __shfl_xor_sync(0xffffffffu, ba, o);
            if (lane == 0) g_bias = ba + bV[0];
        }
    }
    __threadfence();
    __syncthreads();
    if (tid == 0) {
        atomicAdd(&g_syncw, 1);
        int backoff = 32;
        while (atomicAdd(&g_syncw, 0) < NBLK) {
            __nanosleep(backoff);
            if (backoff < 1024) backoff <<= 1;
        }
    }
    __syncthreads();
    __threadfence();   // acquire: all g_w / g_bias writes visible

    // ================= prologue: sw + qb =================
    for (int i = tid; i < HALFn; i += 256) sw[i] = g_w[i];
    {
        float4 q = reinterpret_cast<const float4*>(query + (size_t)b * DQn)[tid];
        float4 w = reinterpret_cast<const float4*>(g_w + HALFn)[tid];
        float p = q.x * w.x + q.y * w.y + q.z * w.z + q.w * w.w;
#pragma unroll
        for (int o = 16; o; o >>= 1) p += __shfl_xor_sync(0xffffffffu, p, o);
        if (lane == 0) red[warp] = p;
    }
    __syncthreads();
    float qb = g_bias;
#pragma unroll
    for (int i = 0; i < 8; i++) qb += red[i];

    int tbase = seg * TS;
    const float* base = values + ((size_t)(b * Tn + tbase)) * Fn;
    const float4* w4 = reinterpret_cast<const float4*>(sw);

    float4 acc[8];
#pragma unroll
    for (int i = 0; i < 8; i++) acc[i] = make_float4(0.f, 0.f, 0.f, 0.f);
    float m = -1e30f, Z = 0.f;

    // ================= streaming loop, double-buffered prefetch =============
    if (isA) {
        float4 va[8], vb[8];
        const float4* rp0 = reinterpret_cast<const float4*>(base + (size_t)pair * Fn);
        LD8(va, rp0);

#define A_BODY(VCUR, VNXT, IT)                                                   \
        {                                                                        \
            int nr = (IT) + 1 < RPP ? (IT) + 1 : RPP - 1;                        \
            const float4* rpn = reinterpret_cast<const float4*>(                 \
                base + (size_t)(nr * PAIRS + pair) * Fn);                        \
            LD8(VNXT, rpn);                                                      \
            float d = 0.f;                                                       \
            _Pragma("unroll")                                                    \
            for (int i = 0; i < 8; i++) {                                        \
                float4 w = w4[lane + 32 * i];                                    \
                d += VCUR[i].x * w.x + VCUR[i].y * w.y                           \
                   + VCUR[i].z * w.z + VCUR[i].w * w.w;                          \
            }                                                                    \
            _Pragma("unroll")                                                    \
            for (int o = 16; o; o >>= 1) d += __shfl_xor_sync(0xffffffffu, d, o);\
            float s = d + qb;                                                    \
            if (lane == 0) g_score[b * Tn + tbase + (IT) * PAIRS + pair] = s;    \
            float c = 1.f;                                                       \
            if (s > m) { c = __expf(m - s); m = s; Z *= c; }                     \
            float e = __expf(s - m);                                             \
            Z += e;                                                              \
            if (lane == 0) { s_e[(IT) & 1][pair] = e; s_c[(IT) & 1][pair] = c; } \
            asm volatile("bar.sync %0, 64;" :: "r"(barid) : "memory");           \
            if (c != 1.f) {                                                      \
                _Pragma("unroll")                                                \
                for (int i = 0; i < 8; i++) {                                    \
                    acc[i].x *= c; acc[i].y *= c; acc[i].z *= c; acc[i].w *= c;  \
                }                                                                \
            }                                                                    \
            _Pragma("unroll")                                                    \
            for (int i = 0; i < 8; i++) {                                        \
                acc[i].x += e * VCUR[i].x; acc[i].y += e * VCUR[i].y;            \
                acc[i].z += e * VCUR[i].z; acc[i].w += e * VCUR[i].w;            \
            }                                                                    \
        }

#pragma unroll 1
        for (int r = 0; r < RPP; r += 2) {
            A_BODY(va, vb, r)
            A_BODY(vb, va, r + 1)
        }
#undef A_BODY
        if (lane == 0) { s_m[pair] = m; s_Z[pair] = Z; }
    } else {
        float4 va[8], vb[8];
        const float4* rp0 = reinterpret_cast<const float4*>(
            base + (size_t)pair * Fn + HALFn);
        LD8(va, rp0);

#define B_BODY(VCUR, VNXT, IT)                                                   \
        {                                                                        \
            int nr = (IT) + 1 < RPP ? (IT) + 1 : RPP - 1;                        \
            const float4* rpn = reinterpret_cast<const float4*>(                 \
                base + (size_t)(nr * PAIRS + pair) * Fn + HALFn);                \
            LD8(VNXT, rpn);                                                      \
            asm volatile("bar.sync %0, 64;" :: "r"(barid) : "memory");           \
            float e = s_e[(IT) & 1][pair];                                       \
            float c = s_c[(IT) & 1][pair];                                       \
            if (c != 1.f) {                                                      \
                _Pragma("unroll")                                                \
                for (int i = 0; i < 8; i++) {                                    \
                    acc[i].x *= c; acc[i].y *= c; acc[i].z *= c; acc[i].w *= c;  \
                }                                                                \
            }                                                                    \
            _Pragma("unroll")                                                    \
            for (int i = 0; i < 8; i++) {                                        \
                acc[i].x += e * VCUR[i].x; acc[i].y += e * VCUR[i].y;            \
                acc[i].z += e * VCUR[i].z; acc[i].w += e * VCUR[i].w;            \
            }                                                                    \
        }

#pragma unroll 1
        for (int r = 0; r < RPP; r += 2) {
            B_BODY(va, vb, r)
            B_BODY(vb, va, r + 1)
        }
#undef B_BODY
    }
    __syncthreads();

    // ---- merge 4 pairs into segment partial ----
    float mseg = s_m[0];
#pragma unroll
    for (int p = 1; p < PAIRS; p++) mseg = fmaxf(mseg, s_m[p]);
    float wt[PAIRS];
    float Zseg = 0.f;
#pragma unroll
    for (int p = 0; p < PAIRS; p++) {
        wt[p] = __expf(s_m[p] - mseg);
        Zseg += s_Z[p] * wt[p];
    }

    float* part = g_partial + ((size_t)(b * SEG + seg)) * Fn;

    if (isA) {
#pragma unroll
        for (int i = 0; i < 8; i++)
            *reinterpret_cast<float4*>(&swacc[pair * HALFn + 4 * (lane + 32 * i)]) = acc[i];
    }
    __syncthreads();
    {
        float4 r = make_float4(0.f, 0.f, 0.f, 0.f);
#pragma unroll
        for (int p = 0; p < PAIRS; p++) {
            float4 c = *reinterpret_cast<const float4*>(&swacc[p * HALFn + 4 * tid]);
            r.x += wt[p] * c.x; r.y += wt[p] * c.y;
            r.z += wt[p] * c.z; r.w += wt[p] * c.w;
        }
        *reinterpret_cast<float4*>(&part[4 * tid]) = r;
    }
    __syncthreads();
    if (!isA) {
#pragma unroll
        for (int i = 0; i < 8; i++)
            *reinterpret_cast<float4*>(&swacc[pair * HALFn + 4 * (lane + 32 * i)]) = acc[i];
    }
    __syncthreads();
    {
        float4 r = make_float4(0.f, 0.f, 0.f, 0.f);
#pragma unroll
        for (int p = 0; p < PAIRS; p++) {
            float4 c = *reinterpret_cast<const float4*>(&swacc[p * HALFn + 4 * tid]);
            r.x += wt[p] * c.x; r.y += wt[p] * c.y;
            r.z += wt[p] * c.z; r.w += wt[p] * c.w;
        }
        *reinterpret_cast<float4*>(&part[HALFn + 4 * tid]) = r;
    }

    if (tid == 0) {
        g_m[b * SEG + seg] = mseg;
        g_Z[b * SEG + seg] = Zseg;
    }

    // ---- fused epilogue: last-arriving block per batch combines ----
    __threadfence();
    __syncthreads();
    if (tid == 0) {
        int prev = atomicAdd(&g_cnt[b], 1);
        s_last = (prev == SEG - 1);
    }
    __syncthreads();
    if (s_last) {
        __threadfence();   // acquire side: partials/scores from peer blocks

        float gm = -1e30f;
#pragma unroll
        for (int s = 0; s < SEG; s++) gm = fmaxf(gm, g_m[b * SEG + s]);
        float Zg = 0.f;
#pragma unroll
        for (int s = 0; s < SEG; s++) Zg += g_Z[b * SEG + s] * __expf(g_m[b * SEG + s] - gm);
        float inv = 1.0f / Zg;

        float4 c0 = make_float4(0.f, 0.f, 0.f, 0.f);
        float4 c1 = make_float4(0.f, 0.f, 0.f, 0.f);
#pragma unroll
        for (int s = 0; s < SEG; s++) {
            float w = __expf(g_m[b * SEG + s] - gm) * inv;
            const float* ps = g_partial + ((size_t)(b * SEG + s)) * Fn;
            float4 p0 = *reinterpret_cast<const float4*>(&ps[4 * tid]);
            float4 p1 = *reinterpret_cast<const float4*>(&ps[HALFn + 4 * tid]);
            c0.x += w * p0.x; c0.y += w * p0.y; c0.z += w * p0.z; c0.w += w * p0.w;
            c1.x += w * p1.x; c1.y += w * p1.y; c1.z += w * p1.z; c1.w += w * p1.w;
        }
        *reinterpret_cast<float4*>(&ctx[(size_t)b * Fn + 4 * tid]) = c0;
        *reinterpret_cast<float4*>(&ctx[(size_t)b * Fn + HALFn + 4 * tid]) = c1;

#pragma unroll
        for (int h = 0; h < 2; h++) {
            int off = h * 1024 + 4 * tid;
            float4 sc = *reinterpret_cast<const float4*>(&g_score[b * Tn + off]);
            float4 r;
            r.x = __expf(sc.x - gm) * inv;
            r.y = __expf(sc.y - gm) * inv;
            r.z = __expf(sc.z - gm) * inv;
            r.w = __expf(sc.w - gm) * inv;
            *reinterpret_cast<float4*>(&aw[b * Tn + off]) = r;
        }

        if (tid == 0) g_cnt[b] = 0;   // reset for next graph replay
    }

    // ---- end-of-kernel reset of the w-phase counter (replay safety) ----
    if (tid == 0) {
        int d = atomicAdd(&g_done, 1);
        if (d == NBLK - 1) {
            g_syncw = 0;
            __threadfence();
            g_done = 0;
        }
    }
}

// ---------------------------------------------------------------------------
extern "C" void kernel_launch(void* const* d_in, const int* in_sizes, int n_in,
                              void* d_out, int out_size) {
    const float* query  = (const float*)d_in[0];
    const float* values = (const float*)d_in[1];
    const float* W1     = (const float*)d_in[2];
    const float* b1     = (const float*)d_in[3];
    const float* V      = (const float*)d_in[4];
    const float* bV     = (const float*)d_in[5];

    float* out = (float*)d_out;
    float* ctx = out;                 // [B, F]   context_vector (32,1,2048)
    float* aw  = out + Bn * Fn;       // [B, T]   attention_weights (32,2048,1)

    dim3 g(SEG, Bn);
    k_all<<<g, 256>>>(values, query, W1, V, b1, bV, ctx, aw);
}

// round 13
// speedup vs baseline: 1.1815x; 1.0250x over previous
#include <cuda_runtime.h>

#define Bn 32
#define Tn 2048
#define Fn 2048
#define DQn 1024
#define UNITSn 1024
#define HALFn 1024      // F/2
#define CONCATn 2048    // HALF + DQ
#define SEG 8           // T segments per batch -> grid 256 = single wave
#define TS (Tn / SEG)   // 256 rows per segment block
#define PAIRS 4         // warp pairs per block (8 warps, 256 threads)
#define RPP (TS / PAIRS) // 64 rows per pair
#define NBLK (SEG * Bn) // 256

// Scratch (allocation-free rule: __device__ globals)
__device__ float g_w[CONCATn];               // W1 @ V
__device__ float g_bias;                     // b1·V + bV
__device__ float g_score[Bn * Tn];           // raw scores
__device__ float g_partial[Bn * SEG * Fn];   // per-seg ctx partials (scale e^{m_seg})
__device__ float g_m[Bn * SEG];              // per-segment max
__device__ float g_Z[Bn * SEG];              // per-segment exp-sum at m_seg
__device__ int   g_cnt[Bn];                  // per-batch arrival counter (self-reset)
__device__ int   g_syncw;                    // w-phase arrival counter
__device__ int   g_done;                     // end-of-kernel counter (resets g_syncw)

#define LD8(dst, ptr)                                            \
    do {                                                         \
        _Pragma("unroll")                                        \
        for (int _i = 0; _i < 8; _i++)                           \
            dst[_i] = __ldcs(&(ptr)[lane + 32 * _i]);            \
    } while (0)

// ---------------------------------------------------------------------------
// Single fused kernel: phase-0 cooperative w = W1@V (+bias), then warp-pair
// specialized single-pass attention processing TWO rows per pair-barrier
// (halved barrier + rescale overhead, 16 LDG.128 burst per iteration),
// fused combine epilogue.
// ---------------------------------------------------------------------------
__global__ __launch_bounds__(256, 2) void k_all(const float* __restrict__ values,
                                                const float* __restrict__ query,
                                                const float* __restrict__ W1,
                                                const float* __restrict__ V,
                                                const float* __restrict__ b1,
                                                const float* __restrict__ bV,
                                                float* __restrict__ ctx,
                                                float* __restrict__ aw) {
    __shared__ float sw[HALFn];                   // 4 KB: w[:1024]
    __shared__ float s_e0[2][PAIRS], s_e1[2][PAIRS], s_c[2][PAIRS];
    __shared__ float s_m[PAIRS], s_Z[PAIRS];
    __shared__ float swacc[PAIRS * HALFn];        // 16 KB merge buffer
    __shared__ float red[8];
    __shared__ int   s_last;

    int seg = blockIdx.x, b = blockIdx.y;
    int bid = b * SEG + seg;                      // 0..255
    int tid = threadIdx.x, warp = tid >> 5, lane = tid & 31;
    int pair = warp >> 1;
    bool isA = (warp & 1) == 0;
    int barid = 1 + pair;

    // ================= phase 0: cooperative w = W1 @ V =================
    {
        int wc = bid * 8 + warp;                  // 0..2047
        const float4* row = reinterpret_cast<const float4*>(W1 + (size_t)wc * UNITSn);
        const float4* v4  = reinterpret_cast<const float4*>(V);
        float acc = 0.f;
#pragma unroll
        for (int i = 0; i < UNITSn / 128; i++) {
            float4 a = row[lane + i * 32];
            float4 v = v4[lane + i * 32];
            acc += a.x * v.x + a.y * v.y + a.z * v.z + a.w * v.w;
        }
#pragma unroll
        for (int o = 16; o; o >>= 1) acc += __shfl_xor_sync(0xffffffffu, acc, o);
        if (lane == 0) g_w[wc] = acc;

        if (bid == 0 && warp == 0) {              // bias = b1·V + bV
            const float4* b4 = reinterpret_cast<const float4*>(b1);
            float ba = 0.f;
#pragma unroll
            for (int i = 0; i < UNITSn / 128; i++) {
                float4 a = b4[lane + i * 32];
                float4 v = v4[lane + i * 32];
                ba += a.x * v.x + a.y * v.y + a.z * v.z + a.w * v.w;
            }
#pragma unroll
            for (int o = 16; o; o >>= 1) ba += __shfl_xor_sync(0xffffffffu, ba, o);
            if (lane == 0) g_bias = ba + bV[0];
        }
    }
    __threadfence();
    __syncthreads();
    if (tid == 0) {
        atomicAdd(&g_syncw, 1);
        int backoff = 32;
        while (atomicAdd(&g_syncw, 0) < NBLK) {
            __nanosleep(backoff);
            if (backoff < 1024) backoff <<= 1;
        }
    }
    __syncthreads();
    __threadfence();   // acquire: all g_w / g_bias writes visible

    // ================= prologue: sw + qb =================
    for (int i = tid; i < HALFn; i += 256) sw[i] = g_w[i];
    {
        float4 q = reinterpret_cast<const float4*>(query + (size_t)b * DQn)[tid];
        float4 w = reinterpret_cast<const float4*>(g_w + HALFn)[tid];
        float p = q.x * w.x + q.y * w.y + q.z * w.z + q.w * w.w;
#pragma unroll
        for (int o = 16; o; o >>= 1) p += __shfl_xor_sync(0xffffffffu, p, o);
        if (lane == 0) red[warp] = p;
    }
    __syncthreads();
    float qb = g_bias;
#pragma unroll
    for (int i = 0; i < 8; i++) qb += red[i];

    int tbase = seg * TS;
    const float* base = values + ((size_t)(b * Tn + tbase)) * Fn;
    const float4* w4 = reinterpret_cast<const float4*>(sw);

    float4 acc[8];
#pragma unroll
    for (int i = 0; i < 8; i++) acc[i] = make_float4(0.f, 0.f, 0.f, 0.f);
    float m = -1e30f, Z = 0.f;

    // ================= streaming loop: 2 rows per barrier =================
    if (isA) {
#pragma unroll 1
        for (int it = 0; it < RPP / 2; it++) {
            int r0 = (2 * it) * PAIRS + pair;
            const float4* rp0 = reinterpret_cast<const float4*>(base + (size_t)r0 * Fn);
            const float4* rp1 = reinterpret_cast<const float4*>(
                base + (size_t)(r0 + PAIRS) * Fn);
            float4 v0[8], v1[8];
            LD8(v0, rp0);
            LD8(v1, rp1);

            float d0 = 0.f, d1 = 0.f;
#pragma unroll
            for (int i = 0; i < 8; i++) {
                float4 w = w4[lane + 32 * i];
                d0 += v0[i].x * w.x + v0[i].y * w.y + v0[i].z * w.z + v0[i].w * w.w;
                d1 += v1[i].x * w.x + v1[i].y * w.y + v1[i].z * w.z + v1[i].w * w.w;
            }
#pragma unroll
            for (int o = 16; o; o >>= 1) {
                d0 += __shfl_xor_sync(0xffffffffu, d0, o);
                d1 += __shfl_xor_sync(0xffffffffu, d1, o);
            }
            float s0 = d0 + qb;
            float s1 = d1 + qb;
            if (lane == 0) {
                __stcs(&g_score[b * Tn + tbase + r0], s0);
                __stcs(&g_score[b * Tn + tbase + r0 + PAIRS], s1);
            }

            float smax = fmaxf(s0, s1);
            float c = 1.f;
            if (smax > m) {              // warp-uniform
                c = __expf(m - smax);
                m = smax;
                Z *= c;
            }
            float e0 = __expf(s0 - m);
            float e1 = __expf(s1 - m);
            Z += e0 + e1;
            if (lane == 0) {
                s_e0[it & 1][pair] = e0;
                s_e1[it & 1][pair] = e1;
                s_c[it & 1][pair]  = c;
            }
            asm volatile("bar.sync %0, 64;" :: "r"(barid) : "memory");

            if (c != 1.f) {
#pragma unroll
                for (int i = 0; i < 8; i++) {
                    acc[i].x *= c; acc[i].y *= c; acc[i].z *= c; acc[i].w *= c;
                }
            }
#pragma unroll
            for (int i = 0; i < 8; i++) {
                acc[i].x += e0 * v0[i].x + e1 * v1[i].x;
                acc[i].y += e0 * v0[i].y + e1 * v1[i].y;
                acc[i].z += e0 * v0[i].z + e1 * v1[i].z;
                acc[i].w += e0 * v0[i].w + e1 * v1[i].w;
            }
        }
        if (lane == 0) { s_m[pair] = m; s_Z[pair] = Z; }
    } else {
#pragma unroll 1
        for (int it = 0; it < RPP / 2; it++) {
            int r0 = (2 * it) * PAIRS + pair;
            const float4* rp0 = reinterpret_cast<const float4*>(
                base + (size_t)r0 * Fn + HALFn);
            const float4* rp1 = reinterpret_cast<const float4*>(
                base + (size_t)(r0 + PAIRS) * Fn + HALFn);
            float4 v0[8], v1[8];
            LD8(v0, rp0);
            LD8(v1, rp1);
            asm volatile("bar.sync %0, 64;" :: "r"(barid) : "memory");
            float e0 = s_e0[it & 1][pair];
            float e1 = s_e1[it & 1][pair];
            float c  = s_c[it & 1][pair];
            if (c != 1.f) {
#pragma unroll
                for (int i = 0; i < 8; i++) {
                    acc[i].x *= c; acc[i].y *= c; acc[i].z *= c; acc[i].w *= c;
                }
            }
#pragma unroll
            for (int i = 0; i < 8; i++) {
                acc[i].x += e0 * v0[i].x + e1 * v1[i].x;
                acc[i].y += e0 * v0[i].y + e1 * v1[i].y;
                acc[i].z += e0 * v0[i].z + e1 * v1[i].z;
                acc[i].w += e0 * v0[i].w + e1 * v1[i].w;
            }
        }
    }
    __syncthreads();

    // ---- merge 4 pairs into segment partial ----
    float mseg = s_m[0];
#pragma unroll
    for (int p = 1; p < PAIRS; p++) mseg = fmaxf(mseg, s_m[p]);
    float wt[PAIRS];
    float Zseg = 0.f;
#pragma unroll
    for (int p = 0; p < PAIRS; p++) {
        wt[p] = __expf(s_m[p] - mseg);
        Zseg += s_Z[p] * wt[p];
    }

    float* part = g_partial + ((size_t)(b * SEG + seg)) * Fn;

    if (isA) {
#pragma unroll
        for (int i = 0; i < 8; i++)
            *reinterpret_cast<float4*>(&swacc[pair * HALFn + 4 * (lane + 32 * i)]) = acc[i];
    }
    __syncthreads();
    {
        float4 r = make_float4(0.f, 0.f, 0.f, 0.f);
#pragma unroll
        for (int p = 0; p < PAIRS; p++) {
            float4 c = *reinterpret_cast<const float4*>(&swacc[p * HALFn + 4 * tid]);
            r.x += wt[p] * c.x; r.y += wt[p] * c.y;
            r.z += wt[p] * c.z; r.w += wt[p] * c.w;
        }
        __stcs(reinterpret_cast<float4*>(&part[4 * tid]), r);
    }
    __syncthreads();
    if (!isA) {
#pragma unroll
        for (int i = 0; i < 8; i++)
            *reinterpret_cast<float4*>(&swacc[pair * HALFn + 4 * (lane + 32 * i)]) = acc[i];
    }
    __syncthreads();
    {
        float4 r = make_float4(0.f, 0.f, 0.f, 0.f);
#pragma unroll
        for (int p = 0; p < PAIRS; p++) {
            float4 c = *reinterpret_cast<const float4*>(&swacc[p * HALFn + 4 * tid]);
            r.x += wt[p] * c.x; r.y += wt[p] * c.y;
            r.z += wt[p] * c.z; r.w += wt[p] * c.w;
        }
        __stcs(reinterpret_cast<float4*>(&part[HALFn + 4 * tid]), r);
    }

    if (tid == 0) {
        g_m[b * SEG + seg] = mseg;
        g_Z[b * SEG + seg] = Zseg;
    }

    // ---- fused epilogue: last-arriving block per batch combines ----
    __threadfence();
    __syncthreads();
    if (tid == 0) {
        int prev = atomicAdd(&g_cnt[b], 1);
        s_last = (prev == SEG - 1);
    }
    __syncthreads();
    if (s_last) {
        __threadfence();   // acquire side: partials/scores from peer blocks

        float gm = -1e30f;
#pragma unroll
        for (int s = 0; s < SEG; s++) gm = fmaxf(gm, g_m[b * SEG + s]);
        float Zg = 0.f;
#pragma unroll
        for (int s = 0; s < SEG; s++) Zg += g_Z[b * SEG + s] * __expf(g_m[b * SEG + s] - gm);
        float inv = 1.0f / Zg;

        float4 c0 = make_float4(0.f, 0.f, 0.f, 0.f);
        float4 c1 = make_float4(0.f, 0.f, 0.f, 0.f);
#pragma unroll
        for (int s = 0; s < SEG; s++) {
            float w = __expf(g_m[b * SEG + s] - gm) * inv;
            const float* ps = g_partial + ((size_t)(b * SEG + s)) * Fn;
            float4 p0 = *reinterpret_cast<const float4*>(&ps[4 * tid]);
            float4 p1 = *reinterpret_cast<const float4*>(&ps[HALFn + 4 * tid]);
            c0.x += w * p0.x; c0.y += w * p0.y; c0.z += w * p0.z; c0.w += w * p0.w;
            c1.x += w * p1.x; c1.y += w * p1.y; c1.z += w * p1.z; c1.w += w * p1.w;
        }
        *reinterpret_cast<float4*>(&ctx[(size_t)b * Fn + 4 * tid]) = c0;
        *reinterpret_cast<float4*>(&ctx[(size_t)b * Fn + HALFn + 4 * tid]) = c1;

#pragma unroll
        for (int h = 0; h < 2; h++) {
            int off = h * 1024 + 4 * tid;
            float4 sc = *reinterpret_cast<const float4*>(&g_score[b * Tn + off]);
            float4 r;
            r.x = __expf(sc.x - gm) * inv;
            r.y = __expf(sc.y - gm) * inv;
            r.z = __expf(sc.z - gm) * inv;
            r.w = __expf(sc.w - gm) * inv;
            *reinterpret_cast<float4*>(&aw[b * Tn + off]) = r;
        }

        if (tid == 0) g_cnt[b] = 0;   // reset for next graph replay
    }

    // ---- end-of-kernel reset of the w-phase counter (replay safety) ----
    if (tid == 0) {
        int d = atomicAdd(&g_done, 1);
        if (d == NBLK - 1) {
            g_syncw = 0;
            __threadfence();
            g_done = 0;
        }
    }
}

// ---------------------------------------------------------------------------
extern "C" void kernel_launch(void* const* d_in, const int* in_sizes, int n_in,
                              void* d_out, int out_size) {
    const float* query  = (const float*)d_in[0];
    const float* values = (const float*)d_in[1];
    const float* W1     = (const float*)d_in[2];
    const float* b1     = (const float*)d_in[3];
    const float* V      = (const float*)d_in[4];
    const float* bV     = (const float*)d_in[5];

    float* out = (float*)d_out;
    float* ctx = out;                 // [B, F]   context_vector (32,1,2048)
    float* aw  = out + Bn * Fn;       // [B, T]   attention_weights (32,2048,1)

    dim3 g(SEG, Bn);
    k_all<<<g, 256>>>(values, query, W1, V, b1, bV, ctx, aw);
}